// round 7
// baseline (speedup 1.0000x reference)
#include <cuda_runtime.h>
#include <math.h>
#include <float.h>

#define BATCH 64
#define NCP   512
#define CPD   64
#define NF    256
#define WS    512
#define SD    128
#define HOP   256
#define NS    65536
#define KT    16             // truncated frame count (contribution <= 1e-14 rel)
#define RLEN  4352           // (KT-1)*HOP + WS

typedef unsigned long long ull;

// ---------------- packed f32x2 helpers (sm_103a FFMA2) ----------------
__device__ __forceinline__ ull pk2(float x, float y){
    ull r; asm("mov.b64 %0, {%1,%2};" : "=l"(r) : "f"(x), "f"(y)); return r;
}
__device__ __forceinline__ void ffma2(ull& d, ull a, ull b){
    asm("fma.rn.f32x2 %0, %1, %2, %0;" : "+l"(d) : "l"(a), "l"(b));
}
__device__ __forceinline__ float2 unpk(ull v){
    float2 r; asm("mov.b64 {%0,%1}, %2;" : "=f"(r.x), "=f"(r.y) : "l"(v)); return r;
}

// ---------------- device scratch (no allocations, 256B-aligned) ----------
__device__ __align__(256) float g_M[KT * CPD * SD];     // rows k*64+c (512 KB)
__device__ __align__(256) float g_projD[CPD * WS];      // proj @ D
__device__ __align__(256) float g_R[CPD * RLEN];        // IR bank (1.1 MB)
__device__ __align__(256) int   g_ic[BATCH * 8];
__device__ __align__(256) int   g_ioff[BATCH * 8];
__device__ __align__(256) float g_iv[BATCH * 8];

__device__ __forceinline__ bool better(float va, int ia, float vb, int ib){
    return (va > vb) || (va == vb && ia < ib);
}

// ============================================================================
// shared 64x32-tile GEMM body (256 threads), K multiple of 64 (static smem)
// ============================================================================
__device__ __forceinline__ void gemm64x32(
    const float* __restrict__ L, int ldL,
    const float* __restrict__ R, int ldR,
    float* __restrict__ O, int ldO,
    int K, int col0)
{
    __shared__ __align__(16) float sA[64][64];
    __shared__ __align__(16) float sB[64][32];
    const int tid = threadIdx.x;
    const int tx = tid & 7;
    const int ty = tid >> 3;
    ull a00 = 0, a01 = 0, a10 = 0, a11 = 0;
    const int ar  = tid & 63;
    const int ak0 = (tid >> 6) * 4;
    const int bc  = (tid & 7) * 4;
    const int bk0 = tid >> 3;

    for (int k0 = 0; k0 < K; k0 += 64){
        #pragma unroll
        for (int kb = 0; kb < 64; kb += 16){
            float4 v = *(const float4*)&L[(size_t)ar * ldL + k0 + kb + ak0];
            sA[kb + ak0 + 0][ar] = v.x; sA[kb + ak0 + 1][ar] = v.y;
            sA[kb + ak0 + 2][ar] = v.z; sA[kb + ak0 + 3][ar] = v.w;
        }
        #pragma unroll
        for (int kb = 0; kb < 64; kb += 32){
            *(float4*)&sB[kb + bk0][bc] =
                *(const float4*)&R[(size_t)(k0 + kb + bk0) * ldR + col0 + bc];
        }
        __syncthreads();
        #pragma unroll 16
        for (int kk = 0; kk < 64; kk++){
            float2 av = *(const float2*)&sA[kk][ty * 2];
            ulonglong2 bv = *(const ulonglong2*)&sB[kk][tx * 4];
            ull p0 = pk2(av.x, av.x), p1 = pk2(av.y, av.y);
            ffma2(a00, p0, bv.x); ffma2(a01, p0, bv.y);
            ffma2(a10, p1, bv.x); ffma2(a11, p1, bv.y);
        }
        __syncthreads();
    }
    float2 t0 = unpk(a00), t1 = unpk(a01), t2 = unpk(a10), t3 = unpk(a11);
    int r = ty * 2, c = col0 + tx * 4;
    float4 o0 = { t0.x, t0.y, t1.x, t1.y };
    float4 o1 = { t2.x, t2.y, t3.x, t3.y };
    *(float4*)&O[(size_t)r * ldO + c]       = o0;
    *(float4*)&O[(size_t)(r + 1) * ldO + c] = o1;
}

// ============================================================================
// K1: front (92 blocks): 0..63 select | 64..79 projD | 80..83 projB | 84..91 zero R
// ============================================================================
__global__ void __launch_bounds__(256) k_front(
    const float* __restrict__ ctrl,
    const float* __restrict__ times,
    const float* __restrict__ lookup,
    const float* __restrict__ proj,
    const float* __restrict__ Bm,
    const float* __restrict__ Dm)
{
    __shared__ __align__(16) float smV[256][8];
    __shared__ __align__(16) int   smI[256][8];
    __shared__ __align__(16) float sv[256];
    __shared__ __align__(16) int   si[256];
    __shared__ int   s_row, s_p;
    __shared__ float s_sum;

    const int bx = blockIdx.x;
    const int tid = threadIdx.x;

    if (bx >= 84){                        // ---- zero R ----
        int base = (bx - 84) * 256 + tid;
        #pragma unroll
        for (int q = 0; q < 34; q++){
            int idx = base + q * 2048;
            if (idx < CPD * RLEN / 4){
                float4 z = {0.f, 0.f, 0.f, 0.f};
                *(float4*)&g_R[idx * 4] = z;
            }
        }
        return;
    }
    if (bx >= 80){                        // ---- projB -> g_M frame 0 ----
        gemm64x32(proj, WS, Bm, SD, g_M, SD, WS, (bx - 80) * 32);
        return;
    }
    if (bx >= BATCH){                     // ---- projD tiles ----
        gemm64x32(proj, WS, Dm, WS, g_projD, WS, WS, (bx - BATCH) * 32);
        return;
    }

    // ---- select: batch b ----
    const int b = bx;
    {
        float v0 = ctrl[b * NCP + tid];
        float v1 = ctrl[b * NCP + 256 + tid];
        float bv = v0; int bi = tid;
        if (better(v1, 256 + tid, bv, bi)){ bv = v1; bi = 256 + tid; }
        sv[tid] = bv; si[tid] = bi;
        for (int s = 128; s > 0; s >>= 1){
            __syncthreads();
            if (tid < s){
                float vo = sv[tid + s]; int io = si[tid + s];
                if (better(vo, io, sv[tid], si[tid])){ sv[tid] = vo; si[tid] = io; }
            }
        }
        __syncthreads();
        if (tid == 0) s_row = si[0];
        __syncthreads();
    }
    {
        sv[tid] = times[b * NF + tid]; si[tid] = tid;
        for (int s = 128; s > 0; s >>= 1){
            __syncthreads();
            if (tid < s){
                float vo = sv[tid + s]; int io = si[tid + s];
                if (better(vo, io, sv[tid], si[tid])){ sv[tid] = vo; si[tid] = io; }
            }
        }
        __syncthreads();
        if (tid == 0) s_p = si[0] * (NS / NF);
    }

    const float* row = lookup + (size_t)s_row * (CPD * NF);

    float tv[8]; int ti[8]; float es = 0.f;
    #pragma unroll
    for (int q = 0; q < 8; q++){ tv[q] = -FLT_MAX; ti[q] = 0x7fffffff; }
    for (int j = tid; j < CPD * NF; j += 256){
        float x = row[j];
        es += __expf(x);
        if (better(x, j, tv[7], ti[7])){
            tv[7] = x; ti[7] = j;
            #pragma unroll
            for (int q = 7; q > 0; q--){
                if (better(tv[q], ti[q], tv[q-1], ti[q-1])){
                    float fv = tv[q]; tv[q] = tv[q-1]; tv[q-1] = fv;
                    int   fi = ti[q]; ti[q] = ti[q-1]; ti[q-1] = fi;
                } else break;
            }
        }
    }
    #pragma unroll
    for (int q = 0; q < 8; q++){ smV[tid][q] = tv[q]; smI[tid][q] = ti[q]; }
    __syncthreads();
    sv[tid] = es;

    for (int s = 128; s > 0; s >>= 1){
        __syncthreads();
        if (tid < s){
            sv[tid] += sv[tid + s];
            int ia = 0, ib = 0;
            float ov[8]; int oi[8];
            #pragma unroll
            for (int t = 0; t < 8; t++){
                float va = smV[tid][ia];     int xa = smI[tid][ia];
                float vb = smV[tid + s][ib]; int xb = smI[tid + s][ib];
                bool pa = better(va, xa, vb, xb);
                ov[t] = pa ? va : vb; oi[t] = pa ? xa : xb;
                ia += pa ? 1 : 0; ib += pa ? 0 : 1;
            }
            #pragma unroll
            for (int t = 0; t < 8; t++){ smV[tid][t] = ov[t]; smI[tid][t] = oi[t]; }
        }
    }
    __syncthreads();
    if (tid == 0) s_sum = sv[0];
    __syncthreads();

    if (tid < 8){
        int idx = smI[0][tid];
        float val = __expf(smV[0][tid]) / s_sum;
        g_ic  [b * 8 + tid] = idx >> 8;
        g_ioff[b * 8 + tid] = s_p + (idx & 255) * HOP;
        g_iv  [b * 8 + tid] = val;
    }
}

// ============================================================================
// K2: recurrence — block c: m_k = m_{k-1} @ A.  A column t in registers,
//     m read as float4 broadcast LDS (32 LDS.128/step, 4 indep FMA chains).
// ============================================================================
__global__ void __launch_bounds__(128) k_rec(const float* __restrict__ A)
{
    __shared__ __align__(16) float ms[2][SD];
    const int c = blockIdx.x;
    const int t = threadIdx.x;

    float a[SD];
    #pragma unroll
    for (int i = 0; i < SD; i++) a[i] = A[i * SD + t];   // column t of A

    ms[0][t] = g_M[c * SD + t];                          // m_0 = projB row c
    __syncthreads();

    #pragma unroll 1
    for (int k = 1; k < KT; k++){
        const float* m = ms[(k - 1) & 1];
        float d0 = 0.f, d1 = 0.f, d2 = 0.f, d3 = 0.f;
        #pragma unroll
        for (int i = 0; i < SD; i += 4){
            float4 mv = *(const float4*)&m[i];          // broadcast LDS.128
            d0 += mv.x * a[i];
            d1 += mv.y * a[i + 1];
            d2 += mv.z * a[i + 2];
            d3 += mv.w * a[i + 3];
        }
        float nm = (d0 + d1) + (d2 + d3);
        ms[k & 1][t] = nm;
        g_M[(size_t)(k * CPD + c) * SD + t] = nm;
        __syncthreads();
    }
}

// ============================================================================
// K3: Q-GEMM (1024x512, K=128) with fused Hann window + scatter-add into R.
//     Each R word receives exactly 2 commutative fp32 adds -> deterministic.
// ============================================================================
__global__ void __launch_bounds__(256) k_gemm2(
    const float* __restrict__ M, const float* __restrict__ C,
    const float* __restrict__ PD)
{
    __shared__ __align__(16) float sA[32][32];
    __shared__ __align__(16) float sB[32][128];
    const int tid  = threadIdx.x;
    const int row0 = blockIdx.x * 32;
    const int col0 = blockIdx.y * 128;
    const int tx = tid & 15;
    const int ty = tid >> 4;
    ull acc[2][4];
    #pragma unroll
    for (int i = 0; i < 2; i++)
        #pragma unroll
        for (int p = 0; p < 4; p++) acc[i][p] = 0ull;

    const int ar = tid & 31;
    const int ak = (tid >> 5) * 4;
    const int bc = (tid & 31) * 4;
    const int bk = tid >> 5;

    for (int k0 = 0; k0 < SD; k0 += 32){
        {
            float4 v = *(const float4*)&M[(size_t)(row0 + ar) * SD + k0 + ak];
            sA[ak + 0][ar] = v.x; sA[ak + 1][ar] = v.y;
            sA[ak + 2][ar] = v.z; sA[ak + 3][ar] = v.w;
        }
        #pragma unroll
        for (int p = 0; p < 4; p++){
            int kk = bk + p * 8;
            *(float4*)&sB[kk][bc] = *(const float4*)&C[(size_t)(k0 + kk) * WS + col0 + bc];
        }
        __syncthreads();
        #pragma unroll
        for (int kk = 0; kk < 32; kk++){
            float2 av = *(const float2*)&sA[kk][ty * 2];
            ulonglong2 bv0 = *(const ulonglong2*)&sB[kk][tx * 8];
            ulonglong2 bv1 = *(const ulonglong2*)&sB[kk][tx * 8 + 4];
            ull p0 = pk2(av.x, av.x), p1 = pk2(av.y, av.y);
            ffma2(acc[0][0], p0, bv0.x); ffma2(acc[0][1], p0, bv0.y);
            ffma2(acc[0][2], p0, bv1.x); ffma2(acc[0][3], p0, bv1.y);
            ffma2(acc[1][0], p1, bv0.x); ffma2(acc[1][1], p1, bv0.y);
            ffma2(acc[1][2], p1, bv1.x); ffma2(acc[1][3], p1, bv1.y);
        }
        __syncthreads();
    }

    const float W = 0.01227184630309f;   // 2*pi/512
    #pragma unroll
    for (int i = 0; i < 2; i++){
        int r = row0 + ty * 2 + i;
        int k = r >> 6;
        int c = r & 63;
        float* dst = &g_R[(size_t)c * RLEN + k * HOP];
        float vals[8];
        float2 u0 = unpk(acc[i][0]), u1 = unpk(acc[i][1]);
        float2 u2 = unpk(acc[i][2]), u3 = unpk(acc[i][3]);
        vals[0] = u0.x; vals[1] = u0.y; vals[2] = u1.x; vals[3] = u1.y;
        vals[4] = u2.x; vals[5] = u2.y; vals[6] = u3.x; vals[7] = u3.y;
        #pragma unroll
        for (int u = 0; u < 8; u++){
            int col = col0 + tx * 8 + u;
            float v = vals[u];
            if (k == 0) v += PD[(size_t)c * WS + col];
            v *= 0.5f * (1.f - __cosf(col * W));
            atomicAdd(dst + col, v);
        }
    }
}

// ============================================================================
// K4: out[b][n] = sum_i v_i * R[c_i][n - off_i]
// ============================================================================
__global__ void k_out(float* __restrict__ out){
    __shared__ __align__(16) int   sc[8];
    __shared__ __align__(16) int   soff[8];
    __shared__ __align__(16) float svv[8];
    const int b = blockIdx.y;
    const int tid = threadIdx.x;
    if (tid < 8){
        sc[tid]   = g_ic[b * 8 + tid];
        soff[tid] = g_ioff[b * 8 + tid];
        svv[tid]  = g_iv[b * 8 + tid];
    }
    __syncthreads();
    const int n = (blockIdx.x * 256 + tid) * 4;
    float4 acc = {0.f, 0.f, 0.f, 0.f};
    #pragma unroll
    for (int i = 0; i < 8; i++){
        int d = n - soff[i];
        if (d >= 0 && d < RLEN){
            float4 r = *(const float4*)&g_R[(size_t)sc[i] * RLEN + d];
            float v = svv[i];
            acc.x += v * r.x; acc.y += v * r.y;
            acc.z += v * r.z; acc.w += v * r.w;
        }
    }
    *(float4*)&out[(size_t)b * NS + n] = acc;
}

// ============================================================================
extern "C" void kernel_launch(void* const* d_in, const int* in_sizes, int n_in,
                              void* d_out, int out_size)
{
    const float* ctrl   = (const float*)d_in[0];
    const float* times  = (const float*)d_in[1];
    const float* lookup = (const float*)d_in[2];
    const float* proj   = (const float*)d_in[3];
    const float* Amat   = (const float*)d_in[4];
    const float* Bm     = (const float*)d_in[5];
    const float* Cm     = (const float*)d_in[6];
    const float* Dm     = (const float*)d_in[7];
    float* out = (float*)d_out;
    (void)in_sizes; (void)n_in; (void)out_size;

    float *pM, *pProjD;
    cudaGetSymbolAddress((void**)&pM,     g_M);
    cudaGetSymbolAddress((void**)&pProjD, g_projD);

    // K1: select + projD + projB(frame 0) + zero R
    k_front<<<92, 256>>>(ctrl, times, lookup, proj, Bm, Dm);

    // K2: SSM recurrence, frames 1..15 (A column in regs, m via LDS.128)
    k_rec<<<CPD, 128>>>(Amat);

    // K3: Q = M @ C (+ projD bias), Hann window + scatter-add into R
    k_gemm2<<<dim3(32, 4), 256>>>(pM, Cm, pProjD);

    // K4: shift-accumulate 8 impulses per batch
    k_out<<<dim3(64, BATCH), 256>>>(out);
}

// round 8
// speedup vs baseline: 1.3845x; 1.3845x over previous
#include <cuda_runtime.h>
#include <math.h>
#include <float.h>

#define BATCH 64
#define NCP   512
#define CPD   64
#define NF    256
#define WS    512
#define SD    128
#define HOP   256
#define NS    65536
#define KT    16             // truncated frame count (contribution <= 1e-14 rel)
#define RLEN  4352           // (KT-1)*HOP + WS

typedef unsigned long long ull;

// ---------------- packed f32x2 helpers (sm_103a FFMA2) ----------------
__device__ __forceinline__ ull pk2(float x, float y){
    ull r; asm("mov.b64 %0, {%1,%2};" : "=l"(r) : "f"(x), "f"(y)); return r;
}
__device__ __forceinline__ void ffma2(ull& d, ull a, ull b){
    asm("fma.rn.f32x2 %0, %1, %2, %0;" : "+l"(d) : "l"(a), "l"(b));
}
__device__ __forceinline__ float2 unpk(ull v){
    float2 r; asm("mov.b64 {%0,%1}, %2;" : "=f"(r.x), "=f"(r.y) : "l"(v)); return r;
}

// ---------------- device scratch (no allocations, 256B-aligned) ----------
__device__ __align__(256) float g_R[CPD * RLEN];        // IR bank (1.1 MB)
__device__ __align__(256) int   g_ic[BATCH * 8];
__device__ __align__(256) int   g_ioff[BATCH * 8];
__device__ __align__(256) float g_iv[BATCH * 8];

__device__ __forceinline__ bool better(float va, int ia, float vb, int ib){
    return (va > vb) || (va == vb && ia < ib);
}

// dyn smem layout (floats) for the channel branch:
//   ps      @ 0      (512)   proj row c
//   pd      @ 512    (512)   projD row c
//   mall    @ 1024   (16*128) m_k bank
//   partial @ 3072   (8*128) m0 warp partials
//   Cs      @ 4096   (32*512) C chunk
//   Qs      @ 20480  (16*512) Q tile
#define SM_PS   0
#define SM_PD   512
#define SM_MALL 1024
#define SM_PART 3072
#define SM_CS   4096
#define SM_QS   20480
#define SM_TOT  28672   // floats -> 114688 bytes

// ============================================================================
// K1: mega kernel (128 blocks, 256 threads)
//   blocks 0..63  : per-batch select (argmax ctrl, argmax times, top-8+expsum)
//   blocks 64..127: channel c = bx-64: m0 = proj@B, pd = proj@D, recurrence,
//                   Q = m_k@C, Hann fold -> g_R[c][:]   (block-exclusive write)
// ============================================================================
__global__ void __launch_bounds__(256) k_mega(
    const float* __restrict__ ctrl,
    const float* __restrict__ times,
    const float* __restrict__ lookup,
    const float* __restrict__ proj,
    const float* __restrict__ Amat,
    const float* __restrict__ Bm,
    const float* __restrict__ Cm,
    const float* __restrict__ Dm)
{
    extern __shared__ __align__(16) float dyn[];
    const int bx  = blockIdx.x;
    const int tid = threadIdx.x;

    if (bx >= BATCH){
        // ======================= channel branch =======================
        const int c = bx - BATCH;
        float* ps   = dyn + SM_PS;
        float* pd   = dyn + SM_PD;
        float* mall = dyn + SM_MALL;
        float* part = dyn + SM_PART;
        float* Cs   = dyn + SM_CS;
        float* Qs   = dyn + SM_QS;

        // --- proj row c -> ps ---
        if (tid < 128)
            *(float4*)&ps[tid * 4] = *(const float4*)&proj[(size_t)c * WS + tid * 4];
        __syncthreads();

        // --- m0 = ps @ B : kg = tid>>5 covers k-range of 64; lane covers 4 states
        {
            const int kg = tid >> 5, lane = tid & 31;
            const int s4 = lane * 4;
            float a0 = 0.f, a1 = 0.f, a2 = 0.f, a3 = 0.f;
            #pragma unroll 8
            for (int kk = 0; kk < 64; kk++){
                int k = kg * 64 + kk;
                float pv = ps[k];
                float4 bv = *(const float4*)&Bm[(size_t)k * SD + s4];
                a0 += pv * bv.x; a1 += pv * bv.y; a2 += pv * bv.z; a3 += pv * bv.w;
            }
            float4 pv4 = { a0, a1, a2, a3 };
            *(float4*)&part[kg * SD + s4] = pv4;
        }
        __syncthreads();
        if (tid < 128){
            float m0 = 0.f;
            #pragma unroll
            for (int kg = 0; kg < 8; kg++) m0 += part[kg * SD + tid];
            mall[tid] = m0;
        }
        __syncthreads();

        // --- pd = ps @ D : thread handles j-pair tid*2 ---
        {
            const int j2 = tid * 2;
            ull dacc = 0ull;
            #pragma unroll 8
            for (int k = 0; k < WS; k++){
                ull dv = *(const ull*)&Dm[(size_t)k * WS + j2];
                ffma2(dacc, pk2(ps[k], ps[k]), dv);
            }
            float2 dr = unpk(dacc);
            pd[j2] = dr.x; pd[j2 + 1] = dr.y;
        }

        // --- recurrence: mall[k] = mall[k-1] @ A  (A column tid in regs) ---
        float a[SD];
        if (tid < 128){
            #pragma unroll
            for (int i = 0; i < SD; i++) a[i] = Amat[i * SD + tid];
        }
        __syncthreads();
        #pragma unroll 1
        for (int k = 1; k < KT; k++){
            if (tid < 128){
                const float* m = &mall[(k - 1) * SD];
                float d0 = 0.f, d1 = 0.f, d2 = 0.f, d3 = 0.f;
                #pragma unroll
                for (int i = 0; i < SD; i += 4){
                    float4 mv = *(const float4*)&m[i];
                    d0 += mv.x * a[i];
                    d1 += mv.y * a[i + 1];
                    d2 += mv.z * a[i + 2];
                    d3 += mv.w * a[i + 3];
                }
                mall[k * SD + tid] = (d0 + d1) + (d2 + d3);
            }
            __syncthreads();
        }

        // --- Q = mall @ C, staged over 4 chunks of 32 s-rows ---
        // thread = (kg = tid>>6 : 4 frames, jg = tid&63 : 8 cols)
        const int kg = tid >> 6;
        const int j0 = (tid & 63) * 8;
        const int k0 = kg * 4;
        ull acc[16];
        #pragma unroll
        for (int q = 0; q < 16; q++) acc[q] = 0ull;

        for (int ch = 0; ch < 4; ch++){
            // load Cs[32][512] (64 KB): 16 float4 per thread
            #pragma unroll
            for (int q = 0; q < 16; q++){
                int idx  = q * 256 + tid;        // float4 index in 4096
                int row  = idx >> 7;             // 128 float4 per row
                int col4 = (idx & 127) * 4;
                *(float4*)&Cs[row * WS + col4] =
                    *(const float4*)&Cm[(size_t)(ch * 32 + row) * WS + col4];
            }
            __syncthreads();
            #pragma unroll 4
            for (int s = 0; s < 32; s++){
                int sg = ch * 32 + s;
                ulonglong2 c01 = *(const ulonglong2*)&Cs[s * WS + j0];
                ulonglong2 c23 = *(const ulonglong2*)&Cs[s * WS + j0 + 4];
                #pragma unroll
                for (int kk = 0; kk < 4; kk++){
                    float mv = mall[(k0 + kk) * SD + sg];   // uniform per warp
                    ull p = pk2(mv, mv);
                    ffma2(acc[kk * 4 + 0], p, c01.x);
                    ffma2(acc[kk * 4 + 1], p, c01.y);
                    ffma2(acc[kk * 4 + 2], p, c23.x);
                    ffma2(acc[kk * 4 + 3], p, c23.y);
                }
            }
            __syncthreads();
        }
        // write Q tile to smem
        #pragma unroll
        for (int kk = 0; kk < 4; kk++){
            #pragma unroll
            for (int jp = 0; jp < 4; jp++){
                *(ull*)&Qs[(k0 + kk) * WS + j0 + jp * 2] = acc[kk * 4 + jp];
            }
        }
        __syncthreads();
        // add projD to frame 0
        Qs[tid]       += pd[tid];
        Qs[tid + 256] += pd[tid + 256];
        __syncthreads();

        // --- Hann fold -> g_R[c][0..RLEN) ---
        const float W = 0.01227184630309f;   // 2*pi/512
        #pragma unroll
        for (int it = 0; it < 5; it++){
            int i4 = it * 256 + tid;
            if (i4 < RLEN / 4){
                int m  = i4 * 4;
                int k1 = m >> 8, j1 = m & 255;
                float c0 = __cosf((j1 + 0) * W);
                float c1 = __cosf((j1 + 1) * W);
                float c2 = __cosf((j1 + 2) * W);
                float c3 = __cosf((j1 + 3) * W);
                float4 o = {0.f, 0.f, 0.f, 0.f};
                if (k1 < KT){
                    float4 v1 = *(const float4*)&Qs[k1 * WS + j1];
                    o.x = 0.5f * (1.f - c0) * v1.x;
                    o.y = 0.5f * (1.f - c1) * v1.y;
                    o.z = 0.5f * (1.f - c2) * v1.z;
                    o.w = 0.5f * (1.f - c3) * v1.w;
                }
                if (k1 > 0){
                    float4 v2 = *(const float4*)&Qs[(k1 - 1) * WS + j1 + 256];
                    o.x += 0.5f * (1.f + c0) * v2.x;
                    o.y += 0.5f * (1.f + c1) * v2.y;
                    o.z += 0.5f * (1.f + c2) * v2.z;
                    o.w += 0.5f * (1.f + c3) * v2.w;
                }
                *(float4*)&g_R[(size_t)c * RLEN + m] = o;
            }
        }
        return;
    }

    // ======================= select branch =======================
    __shared__ __align__(16) float smV[256][8];
    __shared__ __align__(16) int   smI[256][8];
    __shared__ __align__(16) float sv[256];
    __shared__ __align__(16) int   si[256];
    __shared__ int   s_row, s_p;
    __shared__ float s_sum;
    const int b = bx;

    {
        float v0 = ctrl[b * NCP + tid];
        float v1 = ctrl[b * NCP + 256 + tid];
        float bv = v0; int bi = tid;
        if (better(v1, 256 + tid, bv, bi)){ bv = v1; bi = 256 + tid; }
        sv[tid] = bv; si[tid] = bi;
        for (int s = 128; s > 0; s >>= 1){
            __syncthreads();
            if (tid < s){
                float vo = sv[tid + s]; int io = si[tid + s];
                if (better(vo, io, sv[tid], si[tid])){ sv[tid] = vo; si[tid] = io; }
            }
        }
        __syncthreads();
        if (tid == 0) s_row = si[0];
        __syncthreads();
    }
    {
        sv[tid] = times[b * NF + tid]; si[tid] = tid;
        for (int s = 128; s > 0; s >>= 1){
            __syncthreads();
            if (tid < s){
                float vo = sv[tid + s]; int io = si[tid + s];
                if (better(vo, io, sv[tid], si[tid])){ sv[tid] = vo; si[tid] = io; }
            }
        }
        __syncthreads();
        if (tid == 0) s_p = si[0] * (NS / NF);
    }

    const float* row = lookup + (size_t)s_row * (CPD * NF);

    float tv[8]; int ti[8]; float es = 0.f;
    #pragma unroll
    for (int q = 0; q < 8; q++){ tv[q] = -FLT_MAX; ti[q] = 0x7fffffff; }
    for (int j = tid; j < CPD * NF; j += 256){
        float x = row[j];
        es += __expf(x);
        if (better(x, j, tv[7], ti[7])){
            tv[7] = x; ti[7] = j;
            #pragma unroll
            for (int q = 7; q > 0; q--){
                if (better(tv[q], ti[q], tv[q-1], ti[q-1])){
                    float fv = tv[q]; tv[q] = tv[q-1]; tv[q-1] = fv;
                    int   fi = ti[q]; ti[q] = ti[q-1]; ti[q-1] = fi;
                } else break;
            }
        }
    }
    #pragma unroll
    for (int q = 0; q < 8; q++){ smV[tid][q] = tv[q]; smI[tid][q] = ti[q]; }
    __syncthreads();
    sv[tid] = es;

    for (int s = 128; s > 0; s >>= 1){
        __syncthreads();
        if (tid < s){
            sv[tid] += sv[tid + s];
            int ia = 0, ib = 0;
            float ov[8]; int oi[8];
            #pragma unroll
            for (int t = 0; t < 8; t++){
                float va = smV[tid][ia];     int xa = smI[tid][ia];
                float vb = smV[tid + s][ib]; int xb = smI[tid + s][ib];
                bool pa = better(va, xa, vb, xb);
                ov[t] = pa ? va : vb; oi[t] = pa ? xa : xb;
                ia += pa ? 1 : 0; ib += pa ? 0 : 1;
            }
            #pragma unroll
            for (int t = 0; t < 8; t++){ smV[tid][t] = ov[t]; smI[tid][t] = oi[t]; }
        }
    }
    __syncthreads();
    if (tid == 0) s_sum = sv[0];
    __syncthreads();

    if (tid < 8){
        int idx = smI[0][tid];
        float val = __expf(smV[0][tid]) / s_sum;
        g_ic  [b * 8 + tid] = idx >> 8;
        g_ioff[b * 8 + tid] = s_p + (idx & 255) * HOP;
        g_iv  [b * 8 + tid] = val;
    }
}

// ============================================================================
// K2: out[b][n] = sum_i v_i * R[c_i][n - off_i]
// ============================================================================
__global__ void k_out(float* __restrict__ out){
    __shared__ __align__(16) int   sc[8];
    __shared__ __align__(16) int   soff[8];
    __shared__ __align__(16) float svv[8];
    const int b = blockIdx.y;
    const int tid = threadIdx.x;
    if (tid < 8){
        sc[tid]   = g_ic[b * 8 + tid];
        soff[tid] = g_ioff[b * 8 + tid];
        svv[tid]  = g_iv[b * 8 + tid];
    }
    __syncthreads();
    const int n = (blockIdx.x * 256 + tid) * 4;
    float4 acc = {0.f, 0.f, 0.f, 0.f};
    #pragma unroll
    for (int i = 0; i < 8; i++){
        int d = n - soff[i];
        if (d >= 0 && d < RLEN){
            float4 r = *(const float4*)&g_R[(size_t)sc[i] * RLEN + d];
            float v = svv[i];
            acc.x += v * r.x; acc.y += v * r.y;
            acc.z += v * r.z; acc.w += v * r.w;
        }
    }
    *(float4*)&out[(size_t)b * NS + n] = acc;
}

// ============================================================================
extern "C" void kernel_launch(void* const* d_in, const int* in_sizes, int n_in,
                              void* d_out, int out_size)
{
    const float* ctrl   = (const float*)d_in[0];
    const float* times  = (const float*)d_in[1];
    const float* lookup = (const float*)d_in[2];
    const float* proj   = (const float*)d_in[3];
    const float* Amat   = (const float*)d_in[4];
    const float* Bm     = (const float*)d_in[5];
    const float* Cm     = (const float*)d_in[6];
    const float* Dm     = (const float*)d_in[7];
    float* out = (float*)d_out;
    (void)in_sizes; (void)n_in; (void)out_size;

    const int dynBytes = SM_TOT * sizeof(float);   // 114688 B
    cudaFuncSetAttribute(k_mega, cudaFuncAttributeMaxDynamicSharedMemorySize,
                         dynBytes);

    // Node 1: select (64 blocks) + full per-channel pipeline -> R (64 blocks)
    k_mega<<<128, 256, dynBytes>>>(ctrl, times, lookup, proj, Amat, Bm, Cm, Dm);

    // Node 2: shift-accumulate 8 impulses per batch
    k_out<<<dim3(64, BATCH), 256>>>(out);
}